// round 15
// baseline (speedup 1.0000x reference)
#include <cuda_runtime.h>
#include <cuda_fp16.h>
#include <cstdint>

// ---------------------------------------------------------------------------
// BiMambaLayer on GB300 — Round 13: R12 + wide-tile GEMM (BN=128, 256 thr,
// BK=16, 3-stage cp.async) for all large-N GEMMs; xproj keeps BN=64 kernel.
// ---------------------------------------------------------------------------

namespace {
constexpr int kB   = 8;
constexpr int kL   = 4096;
constexpr int kDM  = 512;
constexpr int kDI  = 1024;
constexpr int kDXZ = 2048;
constexpr int kN   = 16;
constexpr int kR   = 32;
constexpr int kDBC = 64;
constexpr int kFF  = 2048;
constexpr int kT   = kB * kL;

constexpr size_t oInF  = 0;
constexpr size_t oInB  = oInF  + 2048 * 512;
constexpr size_t oXpF  = oInB  + 2048 * 512;
constexpr size_t oXpB  = oXpF  + 64 * 1024;
constexpr size_t oDtF  = oXpB  + 64 * 1024;
constexpr size_t oDtB  = oDtF  + 1024 * 32;
constexpr size_t oOutF = oDtB  + 1024 * 32;
constexpr size_t oOutB = oOutF + 512 * 1024;
constexpr size_t oF1   = oOutB + 512 * 1024;
constexpr size_t oF2   = oF1   + 2048 * 512;
constexpr size_t kWH   = oF2   + 512 * 2048;
}

// fp16 activations — forward direction
__device__ __half g_xh   [(size_t)kT * kDM];
__device__ __half g_xzh  [(size_t)kT * kDXZ];   // also ffn hidden
__device__ __half g_xch  [(size_t)kT * kDI];
__device__ __half g_dbch [(size_t)kT * kDBC];
__device__ __half g_dth  [(size_t)kT * kDI];
__device__ __half g_yh   [(size_t)kT * kDI];
// fp16 activations — backward direction
__device__ __half g_xzh2 [(size_t)kT * kDXZ];
__device__ __half g_xch2 [(size_t)kT * kDI];
__device__ __half g_dbch2[(size_t)kT * kDBC];
__device__ __half g_dth2 [(size_t)kT * kDI];
__device__ __half g_yh2  [(size_t)kT * kDI];
__device__ __half g_hh   [(size_t)kT * kDM];
__device__ __half g_wh   [kWH];
// fp32 (output-critical)
__device__ float  g_mf   [(size_t)kT * kDM];    // also ff out
__device__ float  g_mb   [(size_t)kT * kDM];
__device__ float  g_h    [(size_t)kT * kDM];

__device__ __forceinline__ void mma_f16(float* d,
    uint32_t a0, uint32_t a1, uint32_t a2, uint32_t a3,
    uint32_t b0, uint32_t b1)
{
  asm volatile(
    "mma.sync.aligned.m16n8k16.row.col.f32.f16.f16.f32 "
    "{%0,%1,%2,%3}, {%4,%5,%6,%7}, {%8,%9}, {%0,%1,%2,%3};\n"
    : "+f"(d[0]), "+f"(d[1]), "+f"(d[2]), "+f"(d[3])
    : "r"(a0), "r"(a1), "r"(a2), "r"(a3), "r"(b0), "r"(b1));
}
__device__ __forceinline__ void ldsm4(uint32_t* r, uint32_t addr) {
  asm volatile(
    "ldmatrix.sync.aligned.m8n8.x4.shared.b16 {%0,%1,%2,%3}, [%4];"
    : "=r"(r[0]), "=r"(r[1]), "=r"(r[2]), "=r"(r[3]) : "r"(addr));
}
__device__ __forceinline__ void ldsm2(uint32_t& r0, uint32_t& r1, uint32_t addr) {
  asm volatile(
    "ldmatrix.sync.aligned.m8n8.x2.shared.b16 {%0,%1}, [%2];"
    : "=r"(r0), "=r"(r1) : "r"(addr));
}
__device__ __forceinline__ uint32_t pack_h2(float a, float b) {
  __half2 h = __floats2half2_rn(a, b);
  return *reinterpret_cast<uint32_t*>(&h);
}
__device__ __forceinline__ void cpa16(uint32_t s, const void* g) {
  asm volatile("cp.async.cg.shared.global [%0], [%1], 16;" :: "r"(s), "l"(g));
}
__device__ __forceinline__ void cpa_commit() {
  asm volatile("cp.async.commit_group;" ::: "memory");
}
template<int NN>
__device__ __forceinline__ void cpa_wait() {
  asm volatile("cp.async.wait_group %0;" :: "n"(NN) : "memory");
}

// Epilogue activation, shared by both GEMM kernels.
template<int EPI>
__device__ __forceinline__ void epi_apply(float& vx, float& vy,
                                          const float* bias, int c0) {
  if (EPI == 1) {
    vx += __ldg(&bias[c0]);     vy += __ldg(&bias[c0 + 1]);
    vx = fmaxf(vx, 0.f) + log1pf(__expf(-fabsf(vx)));
    vy = fmaxf(vy, 0.f) + log1pf(__expf(-fabsf(vy)));
  } else if (EPI == 2) {
    vx += __ldg(&bias[c0]);     vy += __ldg(&bias[c0 + 1]);
    float tx = tanhf(0.7978845608028654f * (vx + 0.044715f * vx * vx * vx));
    float ty = tanhf(0.7978845608028654f * (vy + 0.044715f * vy * vy * vy));
    vx = 0.5f * vx * (1.f + tx);
    vy = 0.5f * vy * (1.f + ty);
  } else if (EPI == 3) {
    vx += __ldg(&bias[c0]);     vy += __ldg(&bias[c0 + 1]);
  }
}

// Fused fp32 -> fp16 conversion (one launch, up to 12 segments).
struct CvtJobs {
  const float4* src[12];
  uint2* dst[12];
  int n4[12];
  int njobs;
};
__global__ void f2h_all_k(CvtJobs jobs) {
  int j = blockIdx.y;
  if (j >= jobs.njobs) return;
  const float4* s = jobs.src[j];
  uint2* d = jobs.dst[j];
  int n4 = jobs.n4[j];
  for (int i = blockIdx.x * blockDim.x + threadIdx.x; i < n4;
       i += gridDim.x * blockDim.x) {
    float4 v = s[i];
    uint2 o = { pack_h2(v.x, v.y), pack_h2(v.z, v.w) };
    d[i] = o;
  }
}

// ---------------------------------------------------------------------------
// Narrow GEMM (BN=64) — R12-identical. Used only for xproj (N=64).
// ---------------------------------------------------------------------------
template<int EPI, int OUTH>
__global__ void __launch_bounds__(128, 3) gemm_h(
    const __half* __restrict__ A0, const __half* __restrict__ A1, int lda,
    const __half* __restrict__ W0, const __half* __restrict__ W1,
    const float* __restrict__ bias0, const float* __restrict__ bias1,
    void* __restrict__ C0, void* __restrict__ C1, int M, int N, int K)
{
  constexpr int BM = 128, BN = 64, BK = 32, ST2 = 40, STG = 3;
  constexpr int STAGE_H = (BM + BN) * ST2;
  constexpr uint32_t STAGE_B = STAGE_H * 2;
  __shared__ __half Sm[STG * STAGE_H];

  const __half* A    = blockIdx.z ? A1 : A0;
  const __half* W    = blockIdx.z ? W1 : W0;
  const float*  bias = blockIdx.z ? bias1 : bias0;
  void*         Cp   = blockIdx.z ? C1 : C0;

  const int tid  = threadIdx.x;
  const int lane = tid & 31;
  const int wid  = tid >> 5;
  const int wm   = (wid & 1) * 64;
  const int wn   = (wid >> 1) * 32;
  const size_t bm = (size_t)blockIdx.y * BM;
  const int bn   = blockIdx.x * BN;
  const int g4   = lane >> 2;
  const int t4   = lane & 3;
  const int ntiles = K / BK;

  float acc[4][4][4];
  #pragma unroll
  for (int i = 0; i < 4; i++)
    #pragma unroll
    for (int j = 0; j < 4; j++)
      #pragma unroll
      for (int c = 0; c < 4; c++) acc[i][j][c] = 0.f;

  const int ldR = tid >> 2;
  const int ldC = (tid & 3) * 8;

  const __half* aG[4];
  const __half* wG[2];
  uint32_t aDst[4], wDst[2];
  const uint32_t smBase = (uint32_t)__cvta_generic_to_shared(Sm);
  #pragma unroll
  for (int i = 0; i < 4; i++) {
    int r = ldR + 32 * i;
    aG[i]   = &A[(bm + r) * (size_t)lda + ldC];
    aDst[i] = smBase + (uint32_t)((r * ST2 + ldC) * 2);
  }
  #pragma unroll
  for (int i = 0; i < 2; i++) {
    int r = ldR + 32 * i;
    wG[i]   = &W[(size_t)(bn + r) * K + ldC];
    wDst[i] = smBase + (uint32_t)(((BM + r) * ST2 + ldC) * 2);
  }

  auto issue = [&](int stage) {
    const uint32_t so = (uint32_t)stage * STAGE_B;
    #pragma unroll
    for (int i = 0; i < 4; i++) { cpa16(aDst[i] + so, aG[i]); aG[i] += BK; }
    #pragma unroll
    for (int i = 0; i < 2; i++) { cpa16(wDst[i] + so, wG[i]); wG[i] += BK; }
    cpa_commit();
  };

  const int mrow = lane & 7;
  const int mat  = lane >> 3;
  uint32_t aAddr[4], bAddr[4];
  #pragma unroll
  for (int mi = 0; mi < 4; mi++)
    aAddr[mi] = smBase + (uint32_t)(((wm + mi * 16 + (mat & 1) * 8 + mrow) * ST2
                                     + (mat >> 1) * 8) * 2);
  #pragma unroll
  for (int nj = 0; nj < 4; nj++)
    bAddr[nj] = smBase + (uint32_t)(((BM + wn + nj * 8 + mrow) * ST2
                                     + (mat & 1) * 8) * 2);

  if (0 < ntiles) issue(0); else cpa_commit();
  if (1 < ntiles) issue(1); else cpa_commit();

  int stage = 0;
  for (int t = 0; t < ntiles; t++) {
    cpa_wait<1>();
    __syncthreads();
    if (t + 2 < ntiles) issue((stage + 2) % STG); else cpa_commit();

    const uint32_t so = (uint32_t)stage * STAGE_B;
    #pragma unroll
    for (int kk = 0; kk < 2; kk++) {
      uint32_t a[4][4];
      uint32_t b[4][2];
      #pragma unroll
      for (int mi = 0; mi < 4; mi++)
        ldsm4(a[mi], aAddr[mi] + so + (uint32_t)(kk * 32));
      #pragma unroll
      for (int nj = 0; nj < 4; nj++)
        ldsm2(b[nj][0], b[nj][1], bAddr[nj] + so + (uint32_t)(kk * 32));
      #pragma unroll
      for (int mi = 0; mi < 4; mi++)
        #pragma unroll
        for (int nj = 0; nj < 4; nj++)
          mma_f16(acc[mi][nj], a[mi][0], a[mi][1], a[mi][2], a[mi][3],
                  b[nj][0], b[nj][1]);
    }
    stage = (stage + 1 == STG) ? 0 : stage + 1;
  }

  #pragma unroll
  for (int mi = 0; mi < 4; mi++) {
    #pragma unroll
    for (int nj = 0; nj < 4; nj++) {
      size_t r0 = bm + wm + mi * 16 + g4;
      int c0 = bn + wn + nj * 8 + 2 * t4;
      #pragma unroll
      for (int half = 0; half < 2; half++) {
        size_t row = r0 + half * 8;
        float vx = acc[mi][nj][half * 2 + 0];
        float vy = acc[mi][nj][half * 2 + 1];
        epi_apply<EPI>(vx, vy, bias, c0);
        if (OUTH) {
          *reinterpret_cast<uint32_t*>(&((__half*)Cp)[row * (size_t)N + c0]) =
              pack_h2(vx, vy);
        } else {
          float2 v2 = { vx, vy };
          *reinterpret_cast<float2*>(&((float*)Cp)[row * (size_t)N + c0]) = v2;
        }
      }
    }
  }
}

// ---------------------------------------------------------------------------
// Wide GEMM: BM=128, BN=128, BK=16, 256 threads (8 warps 2x4), warp tile
// 64x32, 3-stage cp.async (depth-2). ST2=24 halves (48B rows, LDSM
// conflict-free). Requires M%128==0, N%128==0, K%16==0.
// ---------------------------------------------------------------------------
template<int EPI, int OUTH>
__global__ void __launch_bounds__(256, 2) gemm_w(
    const __half* __restrict__ A0, const __half* __restrict__ A1, int lda,
    const __half* __restrict__ W0, const __half* __restrict__ W1,
    const float* __restrict__ bias0, const float* __restrict__ bias1,
    void* __restrict__ C0, void* __restrict__ C1, int M, int N, int K)
{
  constexpr int BM = 128, BN = 128, BK = 16, ST2 = 24, STG = 3;
  constexpr int STAGE_H = (BM + BN) * ST2;          // 6144 halves
  constexpr uint32_t STAGE_B = STAGE_H * 2;         // 12288 bytes
  __shared__ __half Sm[STG * STAGE_H];              // 36864 B

  const __half* A    = blockIdx.z ? A1 : A0;
  const __half* W    = blockIdx.z ? W1 : W0;
  const float*  bias = blockIdx.z ? bias1 : bias0;
  void*         Cp   = blockIdx.z ? C1 : C0;

  const int tid  = threadIdx.x;
  const int lane = tid & 31;
  const int wid  = tid >> 5;              // 0..7
  const int wm   = (wid & 1) * 64;
  const int wn   = (wid >> 1) * 32;       // 4 n-groups x 32 = 128
  const size_t bm = (size_t)blockIdx.y * BM;
  const int bn   = blockIdx.x * BN;
  const int g4   = lane >> 2;
  const int t4   = lane & 3;
  const int ntiles = K / BK;

  float acc[4][4][4];
  #pragma unroll
  for (int i = 0; i < 4; i++)
    #pragma unroll
    for (int j = 0; j < 4; j++)
      #pragma unroll
      for (int c = 0; c < 4; c++) acc[i][j][c] = 0.f;

  // cp.async: A 128x16 halves = 256x16B -> 1/thread; W 128x16 -> 1/thread.
  const int ldR = tid >> 1;               // 0..127
  const int ldC = (tid & 1) * 8;          // half col 0 or 8

  const __half* aG = &A[(bm + ldR) * (size_t)lda + ldC];
  const __half* wG = &W[(size_t)(bn + ldR) * K + ldC];
  const uint32_t smBase = (uint32_t)__cvta_generic_to_shared(Sm);
  const uint32_t aDst = smBase + (uint32_t)((ldR * ST2 + ldC) * 2);
  const uint32_t wDst = smBase + (uint32_t)(((BM + ldR) * ST2 + ldC) * 2);

  auto issue = [&](int stage) {
    const uint32_t so = (uint32_t)stage * STAGE_B;
    cpa16(aDst + so, aG); aG += BK;
    cpa16(wDst + so, wG); wG += BK;
    cpa_commit();
  };

  const int mrow = lane & 7;
  const int mat  = lane >> 3;
  uint32_t aAddr[4], bAddr[4];
  #pragma unroll
  for (int mi = 0; mi < 4; mi++)
    aAddr[mi] = smBase + (uint32_t)(((wm + mi * 16 + (mat & 1) * 8 + mrow) * ST2
                                     + (mat >> 1) * 8) * 2);
  #pragma unroll
  for (int nj = 0; nj < 4; nj++)
    bAddr[nj] = smBase + (uint32_t)(((BM + wn + nj * 8 + mrow) * ST2
                                     + (mat & 1) * 8) * 2);

  if (0 < ntiles) issue(0); else cpa_commit();
  if (1 < ntiles) issue(1); else cpa_commit();

  int stage = 0;
  for (int t = 0; t < ntiles; t++) {
    cpa_wait<1>();
    __syncthreads();
    if (t + 2 < ntiles) issue((stage + 2) % STG); else cpa_commit();

    const uint32_t so = (uint32_t)stage * STAGE_B;
    uint32_t a[4][4];
    uint32_t b[4][2];
    #pragma unroll
    for (int mi = 0; mi < 4; mi++)
      ldsm4(a[mi], aAddr[mi] + so);
    #pragma unroll
    for (int nj = 0; nj < 4; nj++)
      ldsm2(b[nj][0], b[nj][1], bAddr[nj] + so);
    #pragma unroll
    for (int mi = 0; mi < 4; mi++)
      #pragma unroll
      for (int nj = 0; nj < 4; nj++)
        mma_f16(acc[mi][nj], a[mi][0], a[mi][1], a[mi][2], a[mi][3],
                b[nj][0], b[nj][1]);
    stage = (stage + 1 == STG) ? 0 : stage + 1;
  }

  #pragma unroll
  for (int mi = 0; mi < 4; mi++) {
    #pragma unroll
    for (int nj = 0; nj < 4; nj++) {
      size_t r0 = bm + wm + mi * 16 + g4;
      int c0 = bn + wn + nj * 8 + 2 * t4;
      #pragma unroll
      for (int half = 0; half < 2; half++) {
        size_t row = r0 + half * 8;
        float vx = acc[mi][nj][half * 2 + 0];
        float vy = acc[mi][nj][half * 2 + 1];
        epi_apply<EPI>(vx, vy, bias, c0);
        if (OUTH) {
          *reinterpret_cast<uint32_t*>(&((__half*)Cp)[row * (size_t)N + c0]) =
              pack_h2(vx, vy);
        } else {
          float2 v2 = { vx, vy };
          *reinterpret_cast<float2*>(&((float*)Cp)[row * (size_t)N + c0]) = v2;
        }
      }
    }
  }
}

// ---------------------------------------------------------------------------
// Depthwise causal conv (k=4) + bias + silu; blockIdx.z = direction.
// ---------------------------------------------------------------------------
__global__ void conv_silu_k(const float* __restrict__ cwf,
                            const float* __restrict__ cbf,
                            const float* __restrict__ cwb,
                            const float* __restrict__ cbb)
{
  const int z = blockIdx.z;
  const int dir = z ? -1 : 1;
  const float* cw = z ? cwb : cwf;
  const float* cb = z ? cbb : cbf;
  const __half* src = z ? g_xzh2 : g_xzh;
  __half* dst = z ? g_xch2 : g_xch;

  int i = blockIdx.x * blockDim.x + threadIdx.x;
  int d = i & (kDI - 1);
  int tok = i >> 10;
  int pos = tok & (kL - 1);
  float acc = __ldg(&cb[d]);
  #pragma unroll
  for (int j = 0; j < 4; j++) {
    int o = (dir > 0) ? (j - 3) : (3 - j);
    int p = pos + o;
    if (p >= 0 && p < kL)
      acc = fmaf(__ldg(&cw[d * 4 + j]),
                 __half2float(src[(size_t)(tok + o) * kDXZ + d]), acc);
  }
  dst[i] = __float2half(acc / (1.f + __expf(-acc)));
}

// ---------------------------------------------------------------------------
// Selective scan; blockIdx.z = direction. Warp = 2 channels (16 lanes each).
// ---------------------------------------------------------------------------
__global__ void scan_k(const float* __restrict__ A_log_f,
                       const float* __restrict__ Dp_f,
                       const float* __restrict__ A_log_b,
                       const float* __restrict__ Dp_b)
{
  const int z = blockIdx.z;
  const int dir = z ? -1 : 1;
  const float* A_log = z ? A_log_b : A_log_f;
  const float* Dp    = z ? Dp_b    : Dp_f;
  const __half* dth  = z ? g_dth2  : g_dth;
  const __half* xch  = z ? g_xch2  : g_xch;
  const __half* dbch = z ? g_dbch2 : g_dbch;
  const __half* xzh  = z ? g_xzh2  : g_xzh;
  __half* yh         = z ? g_yh2   : g_yh;

  int gw   = (blockIdx.x * blockDim.x + threadIdx.x) >> 5;
  int lane = threadIdx.x & 31;
  int half = lane >> 4;
  int n    = lane & 15;
  int ch   = gw * 2 + half;
  int b    = ch >> 10;
  int d    = ch & (kDI - 1);

  float A  = -__expf(__ldg(&A_log[d * kN + n]));
  float Dv = __ldg(&Dp[d]);
  float h  = 0.f;
  const size_t tokbase = (size_t)b * kL;

  for (int u = 0; u < kL; ++u) {
    int pos = (dir > 0) ? u : (kL - 1 - u);
    size_t tok = tokbase + pos;
    float dtv = __half2float(dth [tok * kDI  + d]);
    float xv  = __half2float(xch [tok * kDI  + d]);
    float Bv  = __half2float(dbch[tok * kDBC + kR + n]);
    float Cv  = __half2float(dbch[tok * kDBC + kR + kN + n]);
    float a   = __expf(dtv * A);
    h = fmaf(a, h, dtv * xv * Bv);
    float p = h * Cv;
    p += __shfl_xor_sync(0xffffffffu, p, 1);
    p += __shfl_xor_sync(0xffffffffu, p, 2);
    p += __shfl_xor_sync(0xffffffffu, p, 4);
    p += __shfl_xor_sync(0xffffffffu, p, 8);
    if (n == 0) {
      float zv = __half2float(xzh[tok * kDXZ + kDI + d]);
      float sz = zv / (1.f + __expf(-zv));
      yh[tok * kDI + d] = __float2half((p + xv * Dv) * sz);
    }
  }
}

// ---------------------------------------------------------------------------
// LayerNorms
// ---------------------------------------------------------------------------
__device__ __forceinline__ float warp_sum(float v) {
  v += __shfl_xor_sync(0xffffffffu, v, 16);
  v += __shfl_xor_sync(0xffffffffu, v, 8);
  v += __shfl_xor_sync(0xffffffffu, v, 4);
  v += __shfl_xor_sync(0xffffffffu, v, 2);
  v += __shfl_xor_sync(0xffffffffu, v, 1);
  return v;
}

__global__ void ln_combine_k(const float* __restrict__ x,
    const float* __restrict__ gf, const float* __restrict__ bf,
    const float* __restrict__ gb, const float* __restrict__ bb)
{
  int row  = blockIdx.x * (blockDim.x >> 5) + (threadIdx.x >> 5);
  int lane = threadIdx.x & 31;
  const float* xr = x    + (size_t)row * kDM;
  const float* fr = g_mf + (size_t)row * kDM;
  const float* br = g_mb + (size_t)row * kDM;

  float u[16], v[16];
  float su = 0.f, sv = 0.f;
  #pragma unroll
  for (int k = 0; k < 4; k++) {
    int idx = (k * 32 + lane) * 4;
    float4 a  = *reinterpret_cast<const float4*>(xr + idx);
    float4 m1 = *reinterpret_cast<const float4*>(fr + idx);
    float4 m2 = *reinterpret_cast<const float4*>(br + idx);
    u[k*4+0]=a.x+m1.x; u[k*4+1]=a.y+m1.y; u[k*4+2]=a.z+m1.z; u[k*4+3]=a.w+m1.w;
    v[k*4+0]=a.x+m2.x; v[k*4+1]=a.y+m2.y; v[k*4+2]=a.z+m2.z; v[k*4+3]=a.w+m2.w;
    #pragma unroll
    for (int c = 0; c < 4; c++) { su += u[k*4+c]; sv += v[k*4+c]; }
  }
  float muU = warp_sum(su) * (1.f / kDM);
  float muV = warp_sum(sv) * (1.f / kDM);
  float qu = 0.f, qv = 0.f;
  #pragma unroll
  for (int c = 0; c < 16; c++) {
    float du = u[c] - muU, dv = v[c] - muV;
    qu += du * du; qv += dv * dv;
  }
  float rsU = rsqrtf(warp_sum(qu) * (1.f / kDM) + 1e-5f);
  float rsV = rsqrtf(warp_sum(qv) * (1.f / kDM) + 1e-5f);

  float* hr  = g_h  + (size_t)row * kDM;
  __half* hh = g_hh + (size_t)row * kDM;
  #pragma unroll
  for (int k = 0; k < 4; k++) {
    int idx = (k * 32 + lane) * 4;
    float4 o;
    #pragma unroll
    for (int c = 0; c < 4; c++) {
      int f = idx + c;
      float a = (u[k*4+c] - muU) * rsU * __ldg(&gf[f]) + __ldg(&bf[f]);
      float bvv = (v[k*4+c] - muV) * rsV * __ldg(&gb[f]) + __ldg(&bb[f]);
      ((float*)&o)[c] = 0.5f * (a + bvv);
    }
    *reinterpret_cast<float4*>(hr + idx) = o;
    uint2 oh = { pack_h2(o.x, o.y), pack_h2(o.z, o.w) };
    *reinterpret_cast<uint2*>(hh + idx) = oh;
  }
}

__global__ void ln_final_k(const float* __restrict__ ff,
    const float* __restrict__ g, const float* __restrict__ bia,
    float* __restrict__ out)
{
  int row  = blockIdx.x * (blockDim.x >> 5) + (threadIdx.x >> 5);
  int lane = threadIdx.x & 31;
  const float* hr = g_h + (size_t)row * kDM;
  const float* fr = ff  + (size_t)row * kDM;

  float u[16];
  float su = 0.f;
  #pragma unroll
  for (int k = 0; k < 4; k++) {
    int idx = (k * 32 + lane) * 4;
    float4 a  = *reinterpret_cast<const float4*>(hr + idx);
    float4 m1 = *reinterpret_cast<const float4*>(fr + idx);
    u[k*4+0]=a.x+m1.x; u[k*4+1]=a.y+m1.y; u[k*4+2]=a.z+m1.z; u[k*4+3]=a.w+m1.w;
    #pragma unroll
    for (int c = 0; c < 4; c++) su += u[k*4+c];
  }
  float mu = warp_sum(su) * (1.f / kDM);
  float q = 0.f;
  #pragma unroll
  for (int c = 0; c < 16; c++) { float d = u[c] - mu; q += d * d; }
  float rs = rsqrtf(warp_sum(q) * (1.f / kDM) + 1e-5f);

  float* orow = out + (size_t)row * kDM;
  #pragma unroll
  for (int k = 0; k < 4; k++) {
    int idx = (k * 32 + lane) * 4;
    float4 o;
    #pragma unroll
    for (int c = 0; c < 4; c++) {
      int f = idx + c;
      ((float*)&o)[c] = (u[k*4+c] - mu) * rs * __ldg(&g[f]) + __ldg(&bia[f]);
    }
    *reinterpret_cast<float4*>(orow + idx) = o;
  }
}

// ---------------------------------------------------------------------------
// Launch
// ---------------------------------------------------------------------------
extern "C" void kernel_launch(void* const* d_in, const int* in_sizes, int n_in,
                              void* d_out, int out_size)
{
  const float* x = (const float*)d_in[0];
  const float* const* Pf = (const float* const*)&d_in[1];
  const float* const* Pb = (const float* const*)&d_in[10];
  const float* ln_f_g  = (const float*)d_in[19];
  const float* ln_f_b  = (const float*)d_in[20];
  const float* ln_b_g  = (const float*)d_in[21];
  const float* ln_b_b  = (const float*)d_in[22];
  const float* ln_ff_g = (const float*)d_in[23];
  const float* ln_ff_b = (const float*)d_in[24];
  const float* ffn_w1  = (const float*)d_in[25];
  const float* ffn_b1  = (const float*)d_in[26];
  const float* ffn_w2  = (const float*)d_in[27];
  const float* ffn_b2  = (const float*)d_in[28];
  float* out = (float*)d_out;

  void *p_xh, *p_xzh, *p_xch, *p_dbch, *p_dth, *p_yh;
  void *p_xzh2, *p_xch2, *p_dbch2, *p_dth2, *p_yh2;
  void *p_hh, *p_wh, *p_mf, *p_mb, *p_h;
  cudaGetSymbolAddress(&p_xh,    g_xh);
  cudaGetSymbolAddress(&p_xzh,   g_xzh);
  cudaGetSymbolAddress(&p_xch,   g_xch);
  cudaGetSymbolAddress(&p_dbch,  g_dbch);
  cudaGetSymbolAddress(&p_dth,   g_dth);
  cudaGetSymbolAddress(&p_yh,    g_yh);
  cudaGetSymbolAddress(&p_xzh2,  g_xzh2);
  cudaGetSymbolAddress(&p_xch2,  g_xch2);
  cudaGetSymbolAddress(&p_dbch2, g_dbch2);
  cudaGetSymbolAddress(&p_dth2,  g_dth2);
  cudaGetSymbolAddress(&p_yh2,   g_yh2);
  cudaGetSymbolAddress(&p_hh,    g_hh);
  cudaGetSymbolAddress(&p_wh,    g_wh);
  cudaGetSymbolAddress(&p_mf,    g_mf);
  cudaGetSymbolAddress(&p_mb,    g_mb);
  cudaGetSymbolAddress(&p_h,     g_h);
  __half* wh = (__half*)p_wh;
  __half* xh = (__half*)p_xh;

  const dim3 blk128(128), blk256(256);
  const int rowsY = kT / 128;   // 256

  // One fused fp32->fp16 conversion launch (x + 10 weight tensors)
  {
    CvtJobs jobs;
    const float* srcs[11] = { x, Pf[0], Pb[0], Pf[3], Pb[3], Pf[4], Pb[4],
                              Pf[8], Pb[8], ffn_w1, ffn_w2 };
    __half* dsts[11] = { xh, wh + oInF, wh + oInB, wh + oXpF, wh + oXpB,
                         wh + oDtF, wh + oDtB, wh + oOutF, wh + oOutB,
                         wh + oF1, wh + oF2 };
    size_t ns[11] = { (size_t)kT * kDM, 2048*512, 2048*512, 64*1024, 64*1024,
                      1024*32, 1024*32, 512*1024, 512*1024,
                      2048*512, 512*2048 };
    for (int j = 0; j < 11; j++) {
      jobs.src[j] = (const float4*)srcs[j];
      jobs.dst[j] = (uint2*)dsts[j];
      jobs.n4[j]  = (int)(ns[j] / 4);
    }
    jobs.njobs = 11;
    f2h_all_k<<<dim3(2048, 11), blk256>>>(jobs);
  }

  // ---- Batched fwd+bwd mamba pipeline (gridDim.z = 2) ----
  // 1) in_proj: xz = x @ in_w^T          (wide, N=2048)
  gemm_w<0,1><<<dim3(kDXZ / 128, rowsY, 2), blk256>>>(
      xh, xh, kDM, wh + oInF, wh + oInB, nullptr, nullptr,
      p_xzh, p_xzh2, kT, kDXZ, kDM);
  // 2) conv + silu
  conv_silu_k<<<dim3((kT * kDI) / 256, 1, 2), blk256>>>(
      Pf[1], Pf[2], Pb[1], Pb[2]);
  // 3) xproj: dbc = xc @ xproj^T         (narrow, N=64)
  gemm_h<0,1><<<dim3(kDBC / 64, rowsY, 2), blk128>>>(
      (const __half*)p_xch, (const __half*)p_xch2, kDI,
      wh + oXpF, wh + oXpB, nullptr, nullptr,
      p_dbch, p_dbch2, kT, kDBC, kDI);
  // 4) dt = softplus(dbc[:, :32] @ dt_w^T + dt_b)   (wide, N=1024)
  gemm_w<1,1><<<dim3(kDI / 128, rowsY, 2), blk256>>>(
      (const __half*)p_dbch, (const __half*)p_dbch2, kDBC,
      wh + oDtF, wh + oDtB, Pf[5], Pb[5],
      p_dth, p_dth2, kT, kDI, kR);
  // 5) scan
  scan_k<<<dim3(512, 1, 2), blk256>>>(Pf[6], Pf[7], Pb[6], Pb[7]);
  // 6) out_proj: m = y @ out_w^T         (wide, N=512, fp32 out)
  gemm_w<0,0><<<dim3(kDM / 128, rowsY, 2), blk256>>>(
      (const __half*)p_yh, (const __half*)p_yh2, kDI,
      wh + oOutF, wh + oOutB, nullptr, nullptr,
      p_mf, p_mb, kT, kDM, kDI);

  // ---- Combine + FFN + final LN ----
  ln_combine_k<<<kT / 8, blk256>>>(x, ln_f_g, ln_f_b, ln_b_g, ln_b_b);

  gemm_w<2,1><<<dim3(kFF / 128, rowsY, 1), blk256>>>(
      (const __half*)p_hh, (const __half*)p_hh, kDM,
      wh + oF1, wh + oF1, ffn_b1, ffn_b1,
      p_xzh, p_xzh, kT, kFF, kDM);
  gemm_w<3,0><<<dim3(kDM / 128, rowsY, 1), blk256>>>(
      (const __half*)p_xzh, (const __half*)p_xzh, kFF,
      wh + oF2, wh + oF2, ffn_b2, ffn_b2,
      p_mf, p_mf, kT, kDM, kFF);

  ln_final_k<<<kT / 8, blk256>>>((const float*)p_mf, ln_ff_g, ln_ff_b, out);
}